// round 2
// baseline (speedup 1.0000x reference)
#include <cuda_runtime.h>
#include <math.h>

// B=32, N=256, D=256, H=8, K=16
#define BB 32
#define NN 256
#define DD 256
#define HH 8
#define KK 16

#define QOFF 16777216        // B*H*N*N
#define SCALAR_OFF 33554432  // 2*B*H*N*N
#define LOG_EPS -18.420680744f   // log(1e-8)

// scratch (device globals — no allocation allowed)
__device__ __align__(16) float d_Wt[512 * 16];   // W_eff transposed: [j][k]
__device__ __align__(16) float d_beff[16];
__device__ __align__(16) float d_S[BB * NN * KK];
__device__ __align__(16) float d_G[HH * KK * KK];
__device__ float d_greg;
__device__ float d_orth[BB];
__device__ float d_usage[BB];

// ---------------------------------------------------------------------------
// Kernel A: W_eff[k][j] = sum_d W_slot[k,d] * W_fusion[d,j]   (stored as Wt[j][k])
// ---------------------------------------------------------------------------
__global__ void k_weff(const float* __restrict__ Wslot,
                       const float* __restrict__ Wfus) {
    __shared__ float ws[256];
    int k = blockIdx.x >> 1;
    int j = ((blockIdx.x & 1) << 8) + threadIdx.x;
    ws[threadIdx.x] = Wslot[k * 256 + threadIdx.x];
    __syncthreads();
    float acc = 0.f;
#pragma unroll 8
    for (int d = 0; d < 256; ++d) acc += ws[d] * Wfus[d * 512 + j];
    d_Wt[j * 16 + k] = acc;
}

// ---------------------------------------------------------------------------
// Kernel B: G = sinkhorn(softmax(G_param)), zero diag, g_reg, b_eff.  1 block x 256.
// ---------------------------------------------------------------------------
__global__ void k_G(const float* __restrict__ Gp,
                    const float* __restrict__ Wslot,
                    const float* __restrict__ bfus,
                    const float* __restrict__ bslot) {
    __shared__ float g[2048];
    __shared__ float norms[8];
    __shared__ float red[8];
    int tid = threadIdx.x;

#pragma unroll
    for (int h = 0; h < 8; h++) g[h * 256 + tid] = Gp[h * 256 + tid];

    if (tid < 16) {  // b_eff = W_slot @ b_fusion + b_slot
        float s = bslot[tid];
#pragma unroll 8
        for (int d = 0; d < 256; ++d) s += Wslot[tid * 256 + d] * bfus[d];
        d_beff[tid] = s;
    }
    __syncthreads();

    // row softmax then clamp to 1e-6
    if (tid < 128) {
        int base = (tid >> 4) * 256 + (tid & 15) * 16;
        float m = -1e30f;
        for (int j = 0; j < 16; j++) m = fmaxf(m, g[base + j]);
        float e[16], s = 0.f;
        for (int j = 0; j < 16; j++) { e[j] = expf(g[base + j] - m); s += e[j]; }
        float inv = 1.f / s;
        for (int j = 0; j < 16; j++) g[base + j] = fmaxf(e[j] * inv, 1e-6f);
    }
    __syncthreads();

    // sinkhorn: 10 x (row-normalize, col-normalize)
    for (int it = 0; it < 10; ++it) {
        if (tid < 128) {
            int base = (tid >> 4) * 256 + (tid & 15) * 16;
            float s = 0.f;
            for (int j = 0; j < 16; j++) s += g[base + j];
            float inv = 1.f / (s + 1e-6f);
            for (int j = 0; j < 16; j++) g[base + j] *= inv;
        }
        __syncthreads();
        if (tid < 128) {
            int cb = (tid >> 4) * 256 + (tid & 15);
            float s = 0.f;
            for (int i = 0; i < 16; i++) s += g[cb + i * 16];
            float inv = 1.f / (s + 1e-6f);
            for (int i = 0; i < 16; i++) g[cb + i * 16] *= inv;
        }
        __syncthreads();
    }
    if (tid < 128) g[(tid >> 4) * 256 + (tid & 15) * 17] = 0.f;  // zero diag
    __syncthreads();

#pragma unroll
    for (int h = 0; h < 8; h++) d_G[h * 256 + tid] = g[h * 256 + tid];

    // g_reg
    int w = tid >> 5, lane = tid & 31;
    float s = 0.f;
    for (int q = lane; q < 256; q += 32) { float v = g[w * 256 + q]; s += v * v; }
#pragma unroll
    for (int o = 16; o; o >>= 1) s += __shfl_xor_sync(0xffffffffu, s, o);
    if (lane == 0) norms[w] = fmaxf(sqrtf(s), 1e-8f);
    __syncthreads();
    float wv = 0.f;
#pragma unroll
    for (int h = 0; h < 8; h++) wv += g[h * 256 + tid] / norms[h];
    float sq = wv * wv;
#pragma unroll
    for (int o = 16; o; o >>= 1) sq += __shfl_xor_sync(0xffffffffu, sq, o);
    if (lane == 0) red[w] = sq;
    __syncthreads();
    if (tid == 0) {
        float t = 0.f;
        for (int i = 0; i < 8; i++) t += red[i];
        d_greg = 0.02f * (t - 8.0f) / 56.0f;
    }
}

// ---------------------------------------------------------------------------
// Kernel C: S = softmax(X @ W_eff^T + b_eff).  grid 64 x 256, warp does 16 rows.
// Wt smem fill (32KB) amortized over 128 rows/block.
// ---------------------------------------------------------------------------
__global__ void __launch_bounds__(256) k_S(const float* __restrict__ desc,
                                           const float* __restrict__ nv) {
    __shared__ float Wt[512 * 20];
    __shared__ float be[16];
    int tid = threadIdx.x;
    const float4* src = (const float4*)d_Wt;
#pragma unroll
    for (int q = 0; q < 8; q++) {
        int idx = tid + q * 256;        // 2048 float4s
        float4 v = src[idx];
        int j = idx >> 2, c = idx & 3;
        *(float4*)&Wt[j * 20 + c * 4] = v;
    }
    if (tid < 16) be[tid] = d_beff[tid];
    __syncthreads();

    int warp = tid >> 5, lane = tid & 31;
#pragma unroll 1
    for (int rr = 0; rr < 16; ++rr) {
        int row = blockIdx.x * 128 + warp * 16 + rr;
        const float* xd = desc + row * 256;
        const float* xn = nv + row * 256;
        float acc[16];
#pragma unroll
        for (int k = 0; k < 16; k++) acc[k] = 0.f;
#pragma unroll
        for (int jj = 0; jj < 16; jj++) {
            int j = lane + jj * 32;
            float x = (jj < 8) ? xd[j] : xn[j - 256];
            const float* wp = &Wt[j * 20];
            float4 w0 = *(const float4*)(wp);
            float4 w1 = *(const float4*)(wp + 4);
            float4 w2 = *(const float4*)(wp + 8);
            float4 w3 = *(const float4*)(wp + 12);
            acc[0] += x * w0.x; acc[1] += x * w0.y; acc[2] += x * w0.z; acc[3] += x * w0.w;
            acc[4] += x * w1.x; acc[5] += x * w1.y; acc[6] += x * w1.z; acc[7] += x * w1.w;
            acc[8] += x * w2.x; acc[9] += x * w2.y; acc[10] += x * w2.z; acc[11] += x * w2.w;
            acc[12] += x * w3.x; acc[13] += x * w3.y; acc[14] += x * w3.z; acc[15] += x * w3.w;
        }
#pragma unroll
        for (int o = 16; o; o >>= 1)
#pragma unroll
            for (int k = 0; k < 16; k++)
                acc[k] += __shfl_xor_sync(0xffffffffu, acc[k], o);
        float m = -1e30f;
#pragma unroll
        for (int k = 0; k < 16; k++) { acc[k] += be[k]; m = fmaxf(m, acc[k]); }
        float s = 0.f;
#pragma unroll
        for (int k = 0; k < 16; k++) { acc[k] = __expf(acc[k] - m); s += acc[k]; }
        float inv = 1.f / s;
        float myv = 0.f;
#pragma unroll
        for (int k = 0; k < 16; k++)
            if (lane == k) myv = acc[k] * inv;
        if (lane < 16) d_S[row * 16 + lane] = myv;
    }
}

// ---------------------------------------------------------------------------
// Kernel D (dominant): per (b,h,row-chunk of 32): A = (2*S G) S^T, row softmax,
// write Q and bias_log. grid = B*H*8 = 2048 blocks x 256 threads.
// launch_bounds(256,2) -> 2 CTAs/SM -> 16 warps/SM to hide latency.
// Streaming stores keep the 134MB output from thrashing L2.
// ---------------------------------------------------------------------------
__global__ void __launch_bounds__(256, 2) k_Q(float* __restrict__ out) {
    __shared__ __align__(16) float Ss[256 * 20];
    __shared__ float Gs[256];
    __shared__ __align__(16) float SGs[32 * 16];
    int tid = threadIdx.x;
    int bh = blockIdx.x >> 3;
    int chunk = blockIdx.x & 7;
    int b = bh >> 3, h = bh & 7;

    const float4* sp = (const float4*)(d_S + b * 4096);
#pragma unroll
    for (int q = 0; q < 4; q++) {
        float4 v = sp[tid * 4 + q];
        *(float4*)&Ss[tid * 20 + q * 4] = v;   // row tid, chunk q
    }
    Gs[tid] = d_G[h * 256 + tid];
    __syncthreads();

    // SG for this block's 32 rows, pre-scaled by 1/tau = 2
#pragma unroll
    for (int r = 0; r < 2; r++) {
        int e = tid + r * 256;
        int nl = e >> 4, l = e & 15;
        int n = chunk * 32 + nl;
        const float* srow = &Ss[n * 20];
        float s = 0.f;
#pragma unroll
        for (int k = 0; k < 16; k++) s += srow[k] * Gs[k * 16 + l];
        SGs[nl * 16 + l] = 2.0f * s;
    }
    __syncthreads();

    int warp = tid >> 5, lane = tid & 31;
    int n0loc = warp * 4;
#pragma unroll 1
    for (int p = 0; p < 2; p++) {
        int ra = n0loc + p * 2, rb = ra + 1;
        float sg0[16], sg1[16];
        {   // broadcast LDS.128 loads of the two SG rows
            const float4* g0 = (const float4*)&SGs[ra * 16];
            const float4* g1 = (const float4*)&SGs[rb * 16];
#pragma unroll
            for (int q = 0; q < 4; q++) {
                float4 v0 = g0[q], v1 = g1[q];
                sg0[q * 4 + 0] = v0.x; sg0[q * 4 + 1] = v0.y; sg0[q * 4 + 2] = v0.z; sg0[q * 4 + 3] = v0.w;
                sg1[q * 4 + 0] = v1.x; sg1[q * 4 + 1] = v1.y; sg1[q * 4 + 2] = v1.z; sg1[q * 4 + 3] = v1.w;
            }
        }
        float a0[8], a1[8];
#pragma unroll
        for (int c = 0; c < 8; c++) { a0[c] = 0.f; a1[c] = 0.f; }
#pragma unroll
        for (int c = 0; c < 8; c++) {
            int m = lane + c * 32;
            const float* srow = &Ss[m * 20];
            float sv[16];
            *(float4*)&sv[0]  = *(const float4*)(srow);
            *(float4*)&sv[4]  = *(const float4*)(srow + 4);
            *(float4*)&sv[8]  = *(const float4*)(srow + 8);
            *(float4*)&sv[12] = *(const float4*)(srow + 12);
#pragma unroll
            for (int l = 0; l < 16; l++) {
                a0[c] += sg0[l] * sv[l];
                a1[c] += sg1[l] * sv[l];
            }
        }
        // softmax + stores for the 2 rows
#pragma unroll
        for (int rr = 0; rr < 2; rr++) {
            float* a = rr ? a1 : a0;
            int nglob = bh * 256 + chunk * 32 + (rr ? rb : ra);
            float mx = a[0];
#pragma unroll
            for (int c = 1; c < 8; c++) mx = fmaxf(mx, a[c]);
#pragma unroll
            for (int o = 16; o; o >>= 1)
                mx = fmaxf(mx, __shfl_xor_sync(0xffffffffu, mx, o));
            float e[8], s = 0.f;
#pragma unroll
            for (int c = 0; c < 8; c++) { e[c] = __expf(a[c] - mx); s += e[c]; }
#pragma unroll
            for (int o = 16; o; o >>= 1) s += __shfl_xor_sync(0xffffffffu, s, o);
            float inv = 1.f / s;
            float lz = logf(s);
            float* bp = out + (size_t)nglob * 256;          // bias_log
            float* qp = out + QOFF + (size_t)nglob * 256;   // Q
#pragma unroll
            for (int c = 0; c < 8; c++) {
                int m = lane + c * 32;
                __stcs(&qp[m], e[c] * inv);
                __stcs(&bp[m], fmaxf(a[c] - mx - lz, LOG_EPS));
            }
        }
    }
}

// ---------------------------------------------------------------------------
// Kernel E: per-batch regularizer partials (deterministic, no atomics).
// ---------------------------------------------------------------------------
__global__ void k_reg() {
    __shared__ float Ss[4096];
    __shared__ float red[8];
    __shared__ float us[16];
    int b = blockIdx.x, tid = threadIdx.x;
    const float4* sp = (const float4*)(d_S + b * 4096);
#pragma unroll
    for (int q = 0; q < 4; q++) ((float4*)Ss)[tid + q * 256] = sp[tid + q * 256];
    __syncthreads();

    int k = tid >> 4, l = tid & 15;
    float a = 0.f;
#pragma unroll 8
    for (int n = 0; n < 256; n++) a += Ss[n * 16 + k] * Ss[n * 16 + l];
    a *= (1.0f / 256.f);
    float off = (k != l) ? a : 0.f;
    float sq = off * off;
#pragma unroll
    for (int o = 16; o; o >>= 1) sq += __shfl_xor_sync(0xffffffffu, sq, o);
    if ((tid & 31) == 0) red[tid >> 5] = sq;

    if (tid < 16) {
        float u = 0.f;
#pragma unroll 8
        for (int n = 0; n < 256; n++) u += Ss[n * 16 + tid];
        us[tid] = u * (1.0f / 256.f);
    }
    __syncthreads();
    if (tid == 0) {
        float t = 0.f;
        for (int i = 0; i < 8; i++) t += red[i];
        d_orth[b] = 0.1f * t / 8192.0f;
        float usum = 0.f;
        for (int kk = 0; kk < 16; kk++) usum += us[kk];
        float lK = logf(1.0f / 16.0f);
        float kl = 0.f;
        for (int kk = 0; kk < 16; kk++) {
            float uc = fmaxf(us[kk] / (usum + 1e-8f), 1e-8f);
            kl += uc * (logf(uc) - lK);
        }
        d_usage[b] = 0.1f * kl / 32.0f;
    }
}

__global__ void k_final(float* __restrict__ out) {
    if (threadIdx.x == 0) {
        float t = d_greg;
        for (int b = 0; b < 32; b++) t += d_orth[b];
        for (int b = 0; b < 32; b++) t += d_usage[b];
        out[SCALAR_OFF] = t;
    }
}

// ---------------------------------------------------------------------------
extern "C" void kernel_launch(void* const* d_in, const int* in_sizes, int n_in,
                              void* d_out, int out_size) {
    const float* desc  = (const float*)d_in[0];
    const float* nv    = (const float*)d_in[1];
    const float* Wfus  = (const float*)d_in[2];
    const float* bfus  = (const float*)d_in[3];
    const float* Wslot = (const float*)d_in[4];
    const float* bslot = (const float*)d_in[5];
    const float* Gp    = (const float*)d_in[6];
    float* out = (float*)d_out;

    k_weff<<<32, 256>>>(Wslot, Wfus);
    k_G<<<1, 256>>>(Gp, Wslot, bfus, bslot);
    k_S<<<64, 256>>>(desc, nv);
    k_Q<<<BB * HH * 8, 256>>>(out);
    k_reg<<<BB, 256>>>();
    k_final<<<1, 32>>>(out);
}

// round 3
// speedup vs baseline: 1.3131x; 1.3131x over previous
#include <cuda_runtime.h>
#include <math.h>

// B=32, N=256, D=256, H=8, K=16
#define BB 32
#define NN 256
#define HH 8
#define KK 16

#define QOFF 16777216        // B*H*N*N
#define SCALAR_OFF 33554432  // 2*B*H*N*N
#define LOG_EPS -18.420680744f   // log(1e-8)

// scratch (device globals — no allocation allowed)
__device__ __align__(16) float d_Wt[512 * 16];   // W_eff transposed: [j][k]
__device__ __align__(16) float d_beff[16];
__device__ __align__(16) float d_S[BB * NN * KK];
__device__ __align__(16) float d_G[HH * KK * KK];
__device__ float d_greg;
__device__ float d_orth[BB];
__device__ float d_usage[BB];
__device__ int d_cnt;   // zero-init; reset by the finalizing block each launch

// ---------------------------------------------------------------------------
// Kernel PRE (fused): blocks 0-31 compute W_eff; block 32 does sinkhorn(G),
// b_eff and g_reg. Independent work -> runs concurrently in one launch.
// ---------------------------------------------------------------------------
__global__ void k_pre(const float* __restrict__ Wslot,
                      const float* __restrict__ Wfus,
                      const float* __restrict__ Gp,
                      const float* __restrict__ bfus,
                      const float* __restrict__ bslot) {
    int tid = threadIdx.x;
    if (blockIdx.x < 32) {
        // W_eff[k][j] = sum_d W_slot[k,d] * W_fusion[d,j]  (stored Wt[j][k])
        __shared__ float ws[256];
        int k = blockIdx.x >> 1;
        int j = ((blockIdx.x & 1) << 8) + tid;
        ws[tid] = Wslot[k * 256 + tid];
        __syncthreads();
        float acc = 0.f;
#pragma unroll 8
        for (int d = 0; d < 256; ++d) acc += ws[d] * Wfus[d * 512 + j];
        d_Wt[j * 16 + k] = acc;
        return;
    }

    // ---- block 32: G pipeline ----
    __shared__ float g[2048];
    __shared__ float norms[8];
    __shared__ float red[8];

#pragma unroll
    for (int h = 0; h < 8; h++) g[h * 256 + tid] = Gp[h * 256 + tid];

    if (tid < 16) {  // b_eff = W_slot @ b_fusion + b_slot
        float s = bslot[tid];
#pragma unroll 8
        for (int d = 0; d < 256; ++d) s += Wslot[tid * 256 + d] * bfus[d];
        d_beff[tid] = s;
    }
    __syncthreads();

    if (tid < 128) {  // row softmax then clamp
        int base = (tid >> 4) * 256 + (tid & 15) * 16;
        float m = -1e30f;
        for (int j = 0; j < 16; j++) m = fmaxf(m, g[base + j]);
        float e[16], s = 0.f;
        for (int j = 0; j < 16; j++) { e[j] = expf(g[base + j] - m); s += e[j]; }
        float inv = 1.f / s;
        for (int j = 0; j < 16; j++) g[base + j] = fmaxf(e[j] * inv, 1e-6f);
    }
    __syncthreads();

    for (int it = 0; it < 10; ++it) {  // sinkhorn
        if (tid < 128) {
            int base = (tid >> 4) * 256 + (tid & 15) * 16;
            float s = 0.f;
            for (int j = 0; j < 16; j++) s += g[base + j];
            float inv = 1.f / (s + 1e-6f);
            for (int j = 0; j < 16; j++) g[base + j] *= inv;
        }
        __syncthreads();
        if (tid < 128) {
            int cb = (tid >> 4) * 256 + (tid & 15);
            float s = 0.f;
            for (int i = 0; i < 16; i++) s += g[cb + i * 16];
            float inv = 1.f / (s + 1e-6f);
            for (int i = 0; i < 16; i++) g[cb + i * 16] *= inv;
        }
        __syncthreads();
    }
    if (tid < 128) g[(tid >> 4) * 256 + (tid & 15) * 17] = 0.f;  // zero diag
    __syncthreads();

#pragma unroll
    for (int h = 0; h < 8; h++) d_G[h * 256 + tid] = g[h * 256 + tid];

    // g_reg
    int w = tid >> 5, lane = tid & 31;
    float s = 0.f;
    for (int q = lane; q < 256; q += 32) { float v = g[w * 256 + q]; s += v * v; }
#pragma unroll
    for (int o = 16; o; o >>= 1) s += __shfl_xor_sync(0xffffffffu, s, o);
    if (lane == 0) norms[w] = fmaxf(sqrtf(s), 1e-8f);
    __syncthreads();
    float wv = 0.f;
#pragma unroll
    for (int h = 0; h < 8; h++) wv += g[h * 256 + tid] / norms[h];
    float sq = wv * wv;
#pragma unroll
    for (int o = 16; o; o >>= 1) sq += __shfl_xor_sync(0xffffffffu, sq, o);
    if (lane == 0) red[w] = sq;
    __syncthreads();
    if (tid == 0) {
        float t = 0.f;
        for (int i = 0; i < 8; i++) t += red[i];
        d_greg = 0.02f * (t - 8.0f) / 56.0f;
    }
}

// ---------------------------------------------------------------------------
// Kernel C: S = softmax(X @ W_eff^T + b_eff). grid 256 x 256.
// Warp does 4 rows as 2 pairs -> Wt LDS traffic halved vs 1-row.
// ---------------------------------------------------------------------------
__global__ void __launch_bounds__(256) k_S(const float* __restrict__ desc,
                                           const float* __restrict__ nv) {
    __shared__ float Wt[512 * 20];
    __shared__ float be[16];
    int tid = threadIdx.x;
    const float4* src = (const float4*)d_Wt;
#pragma unroll
    for (int q = 0; q < 8; q++) {
        int idx = tid + q * 256;
        float4 v = src[idx];
        int j = idx >> 2, c = idx & 3;
        *(float4*)&Wt[j * 20 + c * 4] = v;
    }
    if (tid < 16) be[tid] = d_beff[tid];
    __syncthreads();

    int warp = tid >> 5, lane = tid & 31;
#pragma unroll 1
    for (int pp = 0; pp < 2; ++pp) {
        int row = blockIdx.x * 32 + warp * 4 + pp * 2;
        const float* xd0 = desc + row * 256;
        const float* xn0 = nv + row * 256;
        float a0[16], a1[16];
#pragma unroll
        for (int k = 0; k < 16; k++) { a0[k] = 0.f; a1[k] = 0.f; }
#pragma unroll
        for (int jj = 0; jj < 16; jj++) {
            int j = lane + jj * 32;
            float x0 = (jj < 8) ? xd0[j] : xn0[j - 256];
            float x1 = (jj < 8) ? xd0[j + 256] : xn0[j];
            const float* wp = &Wt[j * 20];
            float4 w0 = *(const float4*)(wp);
            float4 w1 = *(const float4*)(wp + 4);
            float4 w2 = *(const float4*)(wp + 8);
            float4 w3 = *(const float4*)(wp + 12);
            a0[0] += x0 * w0.x; a0[1] += x0 * w0.y; a0[2] += x0 * w0.z; a0[3] += x0 * w0.w;
            a0[4] += x0 * w1.x; a0[5] += x0 * w1.y; a0[6] += x0 * w1.z; a0[7] += x0 * w1.w;
            a0[8] += x0 * w2.x; a0[9] += x0 * w2.y; a0[10] += x0 * w2.z; a0[11] += x0 * w2.w;
            a0[12] += x0 * w3.x; a0[13] += x0 * w3.y; a0[14] += x0 * w3.z; a0[15] += x0 * w3.w;
            a1[0] += x1 * w0.x; a1[1] += x1 * w0.y; a1[2] += x1 * w0.z; a1[3] += x1 * w0.w;
            a1[4] += x1 * w1.x; a1[5] += x1 * w1.y; a1[6] += x1 * w1.z; a1[7] += x1 * w1.w;
            a1[8] += x1 * w2.x; a1[9] += x1 * w2.y; a1[10] += x1 * w2.z; a1[11] += x1 * w2.w;
            a1[12] += x1 * w3.x; a1[13] += x1 * w3.y; a1[14] += x1 * w3.z; a1[15] += x1 * w3.w;
        }
#pragma unroll
        for (int o = 16; o; o >>= 1) {
#pragma unroll
            for (int k = 0; k < 16; k++) {
                a0[k] += __shfl_xor_sync(0xffffffffu, a0[k], o);
                a1[k] += __shfl_xor_sync(0xffffffffu, a1[k], o);
            }
        }
#pragma unroll
        for (int rr = 0; rr < 2; rr++) {
            float* a = rr ? a1 : a0;
            float m = -1e30f;
#pragma unroll
            for (int k = 0; k < 16; k++) { a[k] += be[k]; m = fmaxf(m, a[k]); }
            float s = 0.f;
#pragma unroll
            for (int k = 0; k < 16; k++) { a[k] = __expf(a[k] - m); s += a[k]; }
            float inv = 1.f / s;
            float myv = 0.f;
#pragma unroll
            for (int k = 0; k < 16; k++)
                if (lane == k) myv = a[k] * inv;
            if (lane < 16) d_S[(row + rr) * 16 + lane] = myv;
        }
    }
}

// ---------------------------------------------------------------------------
// Kernel D (dominant): per (b,h,chunk of 32 rows): A = (2*S G) S^T, row softmax,
// write Q and bias_log. grid 2048 x 256. Warp = 4 rows, K split in halves:
// per step 2xLDS.128 + 32 FFMA (16:1) -> crossbar headroom; ~100 regs, 2 CTA/SM.
// Blocks with (h==0 && chunk==0) also compute per-batch regularizers from smem S;
// the last of those 32 finalizes the scalar.
// ---------------------------------------------------------------------------
__global__ void __launch_bounds__(256, 2) k_Q(float* __restrict__ out) {
    __shared__ __align__(16) float Ss[256 * 20];
    __shared__ float Gs[256];
    __shared__ __align__(16) float SGs[32 * 16];
    __shared__ float red[8];
    __shared__ float us[16];
    int tid = threadIdx.x;
    int bh = blockIdx.x >> 3;
    int chunk = blockIdx.x & 7;
    int b = bh >> 3, h = bh & 7;

    const float4* sp = (const float4*)(d_S + b * 4096);
#pragma unroll
    for (int q = 0; q < 4; q++) {
        float4 v = sp[tid * 4 + q];
        *(float4*)&Ss[tid * 20 + q * 4] = v;   // row tid, chunk q
    }
    Gs[tid] = d_G[h * 256 + tid];
    __syncthreads();

    // SG for this block's 32 rows, pre-scaled by 1/tau = 2
#pragma unroll
    for (int r = 0; r < 2; r++) {
        int e = tid + r * 256;
        int nl = e >> 4, l = e & 15;
        int n = chunk * 32 + nl;
        const float* srow = &Ss[n * 20];
        float s = 0.f;
#pragma unroll
        for (int k = 0; k < 16; k++) s += srow[k] * Gs[k * 16 + l];
        SGs[nl * 16 + l] = 2.0f * s;
    }
    __syncthreads();

    int warp = tid >> 5, lane = tid & 31;
    int r0 = warp * 4;

    float acc[4][8];
#pragma unroll
    for (int r = 0; r < 4; r++)
#pragma unroll
        for (int c = 0; c < 8; c++) acc[r][c] = 0.f;

#pragma unroll
    for (int hf = 0; hf < 2; hf++) {
        float sg[4][8];
#pragma unroll
        for (int r = 0; r < 4; r++) {
            float4 g0 = *(const float4*)&SGs[(r0 + r) * 16 + hf * 8];
            float4 g1 = *(const float4*)&SGs[(r0 + r) * 16 + hf * 8 + 4];
            sg[r][0] = g0.x; sg[r][1] = g0.y; sg[r][2] = g0.z; sg[r][3] = g0.w;
            sg[r][4] = g1.x; sg[r][5] = g1.y; sg[r][6] = g1.z; sg[r][7] = g1.w;
        }
#pragma unroll
        for (int c = 0; c < 8; c++) {
            int m = lane + c * 32;
            const float* srow = &Ss[m * 20 + hf * 8];
            float4 sa = *(const float4*)(srow);
            float4 sb = *(const float4*)(srow + 4);
            float sv[8];
            sv[0] = sa.x; sv[1] = sa.y; sv[2] = sa.z; sv[3] = sa.w;
            sv[4] = sb.x; sv[5] = sb.y; sv[6] = sb.z; sv[7] = sb.w;
#pragma unroll
            for (int r = 0; r < 4; r++)
#pragma unroll
                for (int l = 0; l < 8; l++)
                    acc[r][c] += sg[r][l] * sv[l];
        }
    }

    // softmax + stores, 4 rows
#pragma unroll
    for (int r = 0; r < 4; r++) {
        float mx = acc[r][0];
#pragma unroll
        for (int c = 1; c < 8; c++) mx = fmaxf(mx, acc[r][c]);
#pragma unroll
        for (int o = 16; o; o >>= 1)
            mx = fmaxf(mx, __shfl_xor_sync(0xffffffffu, mx, o));
        float e[8], s = 0.f;
#pragma unroll
        for (int c = 0; c < 8; c++) { e[c] = __expf(acc[r][c] - mx); s += e[c]; }
#pragma unroll
        for (int o = 16; o; o >>= 1) s += __shfl_xor_sync(0xffffffffu, s, o);
        float inv = 1.f / s;
        float lz = __logf(s);
        int nglob = bh * 256 + chunk * 32 + r0 + r;
        float* bp = out + (size_t)nglob * 256;          // bias_log
        float* qp = out + QOFF + (size_t)nglob * 256;   // Q
#pragma unroll
        for (int c = 0; c < 8; c++) {
            int m = lane + c * 32;
            __stcs(&qp[m], e[c] * inv);
            __stcs(&bp[m], fmaxf(acc[r][c] - mx - lz, LOG_EPS));
        }
    }

    // ---- regularizer epilogue on the 32 (h==0, chunk==0) blocks ----
    if ((blockIdx.x & 63) == 0) {
        int k = tid >> 4, l = tid & 15;
        float a = 0.f;
#pragma unroll 8
        for (int n = 0; n < 256; n++) a += Ss[n * 20 + k] * Ss[n * 20 + l];
        a *= (1.0f / 256.f);
        float off = (k != l) ? a : 0.f;
        float sq = off * off;
#pragma unroll
        for (int o = 16; o; o >>= 1) sq += __shfl_xor_sync(0xffffffffu, sq, o);
        if ((tid & 31) == 0) red[tid >> 5] = sq;

        if (tid < 16) {
            float u = 0.f;
#pragma unroll 8
            for (int n = 0; n < 256; n++) u += Ss[n * 20 + tid];
            us[tid] = u * (1.0f / 256.f);
        }
        __syncthreads();
        if (tid == 0) {
            float t = 0.f;
            for (int i = 0; i < 8; i++) t += red[i];
            d_orth[b] = 0.1f * t / 8192.0f;
            float usum = 0.f;
            for (int kk = 0; kk < 16; kk++) usum += us[kk];
            float lK = logf(1.0f / 16.0f);
            float kl = 0.f;
            for (int kk = 0; kk < 16; kk++) {
                float uc = fmaxf(us[kk] / (usum + 1e-8f), 1e-8f);
                kl += uc * (logf(uc) - lK);
            }
            d_usage[b] = 0.1f * kl / 32.0f;
            __threadfence();
            int prev = atomicAdd(&d_cnt, 1);
            if (prev == 31) {   // last one finalizes (deterministic order sum)
                __threadfence();
                float tt = d_greg;
                for (int bb = 0; bb < 32; bb++) tt += d_orth[bb];
                for (int bb = 0; bb < 32; bb++) tt += d_usage[bb];
                out[SCALAR_OFF] = tt;
                d_cnt = 0;      // reset for next replay
            }
        }
    }
}

// ---------------------------------------------------------------------------
extern "C" void kernel_launch(void* const* d_in, const int* in_sizes, int n_in,
                              void* d_out, int out_size) {
    const float* desc  = (const float*)d_in[0];
    const float* nv    = (const float*)d_in[1];
    const float* Wfus  = (const float*)d_in[2];
    const float* bfus  = (const float*)d_in[3];
    const float* Wslot = (const float*)d_in[4];
    const float* bslot = (const float*)d_in[5];
    const float* Gp    = (const float*)d_in[6];
    float* out = (float*)d_out;

    k_pre<<<33, 256>>>(Wslot, Wfus, Gp, bfus, bslot);
    k_S<<<256, 256>>>(desc, nv);
    k_Q<<<BB * HH * 8, 256>>>(out);
}

// round 4
// speedup vs baseline: 2.2443x; 1.7091x over previous
#include <cuda_runtime.h>
#include <math.h>

// B=32, N=256, D=256, H=8, K=16
#define BB 32
#define NN 256
#define HH 8
#define KK 16

#define QOFF 16777216        // B*H*N*N
#define SCALAR_OFF 33554432  // 2*B*H*N*N
#define LOG_EPS -18.420680744f   // log(1e-8)

// scratch (device globals — no allocation allowed)
__device__ __align__(16) float d_Wt[512 * 16];   // W_eff transposed: [j][k]
__device__ __align__(16) float d_beff[16];
__device__ __align__(16) float d_S[BB * NN * KK];
__device__ __align__(16) float d_G[HH * KK * KK];
__device__ float d_greg;
__device__ float d_orth[BB];
__device__ float d_usage[BB];
__device__ int d_cnt;   // zero-init; reset by the finalizing block each launch

// ---------------------------------------------------------------------------
// Kernel PRE (fused): blocks 0-31 compute W_eff (deep-MLP loads); block 32 does
// registerized sinkhorn(G) + g_reg (warps 0-3) and b_eff (warps 4-7).
// ---------------------------------------------------------------------------
__global__ void __launch_bounds__(256) k_pre(const float* __restrict__ Wslot,
                      const float* __restrict__ Wfus,
                      const float* __restrict__ Gp,
                      const float* __restrict__ bfus,
                      const float* __restrict__ bslot) {
    int tid = threadIdx.x;
    if (blockIdx.x < 32) {
        // W_eff[k][j] = sum_d W_slot[k,d] * W_fusion[d,j]  (stored Wt[j][k])
        __shared__ float ws[256];
        int k = blockIdx.x >> 1;
        int j = ((blockIdx.x & 1) << 8) + tid;
        ws[tid] = Wslot[k * 256 + tid];
        __syncthreads();
        float a0 = 0.f, a1 = 0.f, a2 = 0.f, a3 = 0.f;
#pragma unroll
        for (int d0 = 0; d0 < 256; d0 += 32) {
            float v[32];
#pragma unroll
            for (int u = 0; u < 32; u++) v[u] = Wfus[(d0 + u) * 512 + j];
#pragma unroll
            for (int u = 0; u < 32; u += 4) {
                a0 += ws[d0 + u]     * v[u];
                a1 += ws[d0 + u + 1] * v[u + 1];
                a2 += ws[d0 + u + 2] * v[u + 2];
                a3 += ws[d0 + u + 3] * v[u + 3];
            }
        }
        d_Wt[j * 16 + k] = (a0 + a1) + (a2 + a3);
        return;
    }

    // ---- block 32 ----
    __shared__ __align__(16) float sv[128 * 16];   // normalized V rows
    __shared__ float red[8];

    if (tid >= 128) {
        // warps 4-7: b_eff = W_slot @ b_fusion + b_slot  (coalesced, parallel)
        int w = (tid >> 5) - 4;        // 0..3
        int lane = tid & 31;
        int kg = w * 4;
        float acc[4] = {0.f, 0.f, 0.f, 0.f};
#pragma unroll
        for (int i = 0; i < 8; i++) {
            int d = i * 32 + lane;
            float bf = bfus[d];
#pragma unroll
            for (int kk = 0; kk < 4; kk++)
                acc[kk] += Wslot[(kg + kk) * 256 + d] * bf;
        }
#pragma unroll
        for (int o = 16; o; o >>= 1)
#pragma unroll
            for (int kk = 0; kk < 4; kk++)
                acc[kk] += __shfl_xor_sync(0xffffffffu, acc[kk], o);
        if (lane < 4) d_beff[kg + lane] = acc[lane] + bslot[kg + lane];
    } else {
        // warps 0-3: registerized sinkhorn. thread r owns G row r (16 floats).
        int r = tid;                  // 0..127 = h*16 + i
        float g[16];
        {
            const float4* gp = (const float4*)(Gp + r * 16);
            float4 v0 = gp[0], v1 = gp[1], v2 = gp[2], v3 = gp[3];
            g[0] = v0.x; g[1] = v0.y; g[2] = v0.z; g[3] = v0.w;
            g[4] = v1.x; g[5] = v1.y; g[6] = v1.z; g[7] = v1.w;
            g[8] = v2.x; g[9] = v2.y; g[10] = v2.z; g[11] = v2.w;
            g[12] = v3.x; g[13] = v3.y; g[14] = v3.z; g[15] = v3.w;
        }
        // row softmax + clamp
        float m = g[0];
#pragma unroll
        for (int j = 1; j < 16; j++) m = fmaxf(m, g[j]);
        float s = 0.f;
#pragma unroll
        for (int j = 0; j < 16; j++) { g[j] = expf(g[j] - m); s += g[j]; }
        float inv = 1.f / s;
#pragma unroll
        for (int j = 0; j < 16; j++) g[j] = fmaxf(g[j] * inv, 1e-6f);

        // 10 sinkhorn iterations, no block sync: col sums via 16-lane butterfly
#pragma unroll 1
        for (int it = 0; it < 10; ++it) {
            float rs = 0.f;
#pragma unroll
            for (int j = 0; j < 16; j++) rs += g[j];
            float rinv = 1.f / (rs + 1e-6f);
#pragma unroll
            for (int j = 0; j < 16; j++) g[j] *= rinv;
            float c[16];
#pragma unroll
            for (int j = 0; j < 16; j++) c[j] = g[j];
#pragma unroll
            for (int o = 8; o; o >>= 1)
#pragma unroll
                for (int j = 0; j < 16; j++)
                    c[j] += __shfl_xor_sync(0xffffffffu, c[j], o);
#pragma unroll
            for (int j = 0; j < 16; j++) g[j] *= 1.f / (c[j] + 1e-6f);
        }
        // zero diagonal: row i within head kills column i
        g[r & 15] = 0.f;
        // store G
        {
            float4* gp = (float4*)(d_G + r * 16);
            gp[0] = make_float4(g[0], g[1], g[2], g[3]);
            gp[1] = make_float4(g[4], g[5], g[6], g[7]);
            gp[2] = make_float4(g[8], g[9], g[10], g[11]);
            gp[3] = make_float4(g[12], g[13], g[14], g[15]);
        }
        // head Frobenius norm: butterfly within the 16-lane head group
        float sq = 0.f;
#pragma unroll
        for (int j = 0; j < 16; j++) sq += g[j] * g[j];
#pragma unroll
        for (int o = 8; o; o >>= 1) sq += __shfl_xor_sync(0xffffffffu, sq, o);
        float ninv = 1.f / fmaxf(sqrtf(sq), 1e-8f);
        float4* svp = (float4*)&sv[r * 16];
        svp[0] = make_float4(g[0] * ninv, g[1] * ninv, g[2] * ninv, g[3] * ninv);
        svp[1] = make_float4(g[4] * ninv, g[5] * ninv, g[6] * ninv, g[7] * ninv);
        svp[2] = make_float4(g[8] * ninv, g[9] * ninv, g[10] * ninv, g[11] * ninv);
        svp[3] = make_float4(g[12] * ninv, g[13] * ninv, g[14] * ninv, g[15] * ninv);
    }
    __syncthreads();

    // g_reg = 0.02*(||sum_h V_h||^2 - 8)/56 ; 256 threads, one (i,j) each
    {
        int il = tid >> 4, j = tid & 15;
        float wv = 0.f;
#pragma unroll
        for (int h = 0; h < 8; h++) wv += sv[(h * 16 + il) * 16 + j];
        float sq = wv * wv;
#pragma unroll
        for (int o = 16; o; o >>= 1) sq += __shfl_xor_sync(0xffffffffu, sq, o);
        if ((tid & 31) == 0) red[tid >> 5] = sq;
        __syncthreads();
        if (tid == 0) {
            float t = 0.f;
            for (int i = 0; i < 8; i++) t += red[i];
            d_greg = 0.02f * (t - 8.0f) / 56.0f;
        }
    }
}

// ---------------------------------------------------------------------------
// Kernel C: S = softmax(X @ W_eff^T + b_eff). grid 256 x 256.
// Warp does 4 rows as 2 pairs -> Wt LDS traffic halved vs 1-row.
// ---------------------------------------------------------------------------
__global__ void __launch_bounds__(256) k_S(const float* __restrict__ desc,
                                           const float* __restrict__ nv) {
    __shared__ float Wt[512 * 20];
    __shared__ float be[16];
    int tid = threadIdx.x;
    const float4* src = (const float4*)d_Wt;
#pragma unroll
    for (int q = 0; q < 8; q++) {
        int idx = tid + q * 256;
        float4 v = src[idx];
        int j = idx >> 2, c = idx & 3;
        *(float4*)&Wt[j * 20 + c * 4] = v;
    }
    if (tid < 16) be[tid] = d_beff[tid];
    __syncthreads();

    int warp = tid >> 5, lane = tid & 31;
#pragma unroll 1
    for (int pp = 0; pp < 2; ++pp) {
        int row = blockIdx.x * 32 + warp * 4 + pp * 2;
        const float* xd0 = desc + row * 256;
        const float* xn0 = nv + row * 256;
        float a0[16], a1[16];
#pragma unroll
        for (int k = 0; k < 16; k++) { a0[k] = 0.f; a1[k] = 0.f; }
#pragma unroll
        for (int jj = 0; jj < 16; jj++) {
            int j = lane + jj * 32;
            float x0 = (jj < 8) ? xd0[j] : xn0[j - 256];
            float x1 = (jj < 8) ? xd0[j + 256] : xn0[j];
            const float* wp = &Wt[j * 20];
            float4 w0 = *(const float4*)(wp);
            float4 w1 = *(const float4*)(wp + 4);
            float4 w2 = *(const float4*)(wp + 8);
            float4 w3 = *(const float4*)(wp + 12);
            a0[0] += x0 * w0.x; a0[1] += x0 * w0.y; a0[2] += x0 * w0.z; a0[3] += x0 * w0.w;
            a0[4] += x0 * w1.x; a0[5] += x0 * w1.y; a0[6] += x0 * w1.z; a0[7] += x0 * w1.w;
            a0[8] += x0 * w2.x; a0[9] += x0 * w2.y; a0[10] += x0 * w2.z; a0[11] += x0 * w2.w;
            a0[12] += x0 * w3.x; a0[13] += x0 * w3.y; a0[14] += x0 * w3.z; a0[15] += x0 * w3.w;
            a1[0] += x1 * w0.x; a1[1] += x1 * w0.y; a1[2] += x1 * w0.z; a1[3] += x1 * w0.w;
            a1[4] += x1 * w1.x; a1[5] += x1 * w1.y; a1[6] += x1 * w1.z; a1[7] += x1 * w1.w;
            a1[8] += x1 * w2.x; a1[9] += x1 * w2.y; a1[10] += x1 * w2.z; a1[11] += x1 * w2.w;
            a1[12] += x1 * w3.x; a1[13] += x1 * w3.y; a1[14] += x1 * w3.z; a1[15] += x1 * w3.w;
        }
#pragma unroll
        for (int o = 16; o; o >>= 1) {
#pragma unroll
            for (int k = 0; k < 16; k++) {
                a0[k] += __shfl_xor_sync(0xffffffffu, a0[k], o);
                a1[k] += __shfl_xor_sync(0xffffffffu, a1[k], o);
            }
        }
#pragma unroll
        for (int rr = 0; rr < 2; rr++) {
            float* a = rr ? a1 : a0;
            float m = -1e30f;
#pragma unroll
            for (int k = 0; k < 16; k++) { a[k] += be[k]; m = fmaxf(m, a[k]); }
            float s = 0.f;
#pragma unroll
            for (int k = 0; k < 16; k++) { a[k] = __expf(a[k] - m); s += a[k]; }
            float inv = 1.f / s;
            float myv = 0.f;
#pragma unroll
            for (int k = 0; k < 16; k++)
                if (lane == k) myv = a[k] * inv;
            if (lane < 16) d_S[(row + rr) * 16 + lane] = myv;
        }
    }
}

// ---------------------------------------------------------------------------
// Kernel D (dominant): per (b,h,chunk of 32 rows): A = (2*S G) S^T, row softmax,
// write Q and bias_log. grid 2048 x 256. Warp = 4 rows, K split in halves.
// (h==0,chunk==0) blocks also do per-batch regularizers; last one finalizes.
// ---------------------------------------------------------------------------
__global__ void __launch_bounds__(256, 2) k_Q(float* __restrict__ out) {
    __shared__ __align__(16) float Ss[256 * 20];
    __shared__ float Gs[256];
    __shared__ __align__(16) float SGs[32 * 16];
    __shared__ float red[8];
    __shared__ float us[16];
    int tid = threadIdx.x;
    int bh = blockIdx.x >> 3;
    int chunk = blockIdx.x & 7;
    int b = bh >> 3, h = bh & 7;

    const float4* sp = (const float4*)(d_S + b * 4096);
#pragma unroll
    for (int q = 0; q < 4; q++) {
        float4 v = sp[tid * 4 + q];
        *(float4*)&Ss[tid * 20 + q * 4] = v;   // row tid, chunk q
    }
    Gs[tid] = d_G[h * 256 + tid];
    __syncthreads();

    // SG for this block's 32 rows, pre-scaled by 1/tau = 2
#pragma unroll
    for (int r = 0; r < 2; r++) {
        int e = tid + r * 256;
        int nl = e >> 4, l = e & 15;
        int n = chunk * 32 + nl;
        const float* srow = &Ss[n * 20];
        float s = 0.f;
#pragma unroll
        for (int k = 0; k < 16; k++) s += srow[k] * Gs[k * 16 + l];
        SGs[nl * 16 + l] = 2.0f * s;
    }
    __syncthreads();

    int warp = tid >> 5, lane = tid & 31;
    int r0 = warp * 4;

    float acc[4][8];
#pragma unroll
    for (int r = 0; r < 4; r++)
#pragma unroll
        for (int c = 0; c < 8; c++) acc[r][c] = 0.f;

#pragma unroll
    for (int hf = 0; hf < 2; hf++) {
        float sg[4][8];
#pragma unroll
        for (int r = 0; r < 4; r++) {
            float4 g0 = *(const float4*)&SGs[(r0 + r) * 16 + hf * 8];
            float4 g1 = *(const float4*)&SGs[(r0 + r) * 16 + hf * 8 + 4];
            sg[r][0] = g0.x; sg[r][1] = g0.y; sg[r][2] = g0.z; sg[r][3] = g0.w;
            sg[r][4] = g1.x; sg[r][5] = g1.y; sg[r][6] = g1.z; sg[r][7] = g1.w;
        }
#pragma unroll
        for (int c = 0; c < 8; c++) {
            int m = lane + c * 32;
            const float* srow = &Ss[m * 20 + hf * 8];
            float4 sa = *(const float4*)(srow);
            float4 sb = *(const float4*)(srow + 4);
            float sv[8];
            sv[0] = sa.x; sv[1] = sa.y; sv[2] = sa.z; sv[3] = sa.w;
            sv[4] = sb.x; sv[5] = sb.y; sv[6] = sb.z; sv[7] = sb.w;
#pragma unroll
            for (int r = 0; r < 4; r++)
#pragma unroll
                for (int l = 0; l < 8; l++)
                    acc[r][c] += sg[r][l] * sv[l];
        }
    }

    // softmax + stores, 4 rows
#pragma unroll
    for (int r = 0; r < 4; r++) {
        float mx = acc[r][0];
#pragma unroll
        for (int c = 1; c < 8; c++) mx = fmaxf(mx, acc[r][c]);
#pragma unroll
        for (int o = 16; o; o >>= 1)
            mx = fmaxf(mx, __shfl_xor_sync(0xffffffffu, mx, o));
        float e[8], s = 0.f;
#pragma unroll
        for (int c = 0; c < 8; c++) { e[c] = __expf(acc[r][c] - mx); s += e[c]; }
#pragma unroll
        for (int o = 16; o; o >>= 1) s += __shfl_xor_sync(0xffffffffu, s, o);
        float inv = 1.f / s;
        float lz = __logf(s);
        int nglob = bh * 256 + chunk * 32 + r0 + r;
        float* bp = out + (size_t)nglob * 256;          // bias_log
        float* qp = out + QOFF + (size_t)nglob * 256;   // Q
#pragma unroll
        for (int c = 0; c < 8; c++) {
            int m = lane + c * 32;
            __stcs(&qp[m], e[c] * inv);
            __stcs(&bp[m], fmaxf(acc[r][c] - mx - lz, LOG_EPS));
        }
    }

    // ---- regularizer epilogue on the 32 (h==0, chunk==0) blocks ----
    if ((blockIdx.x & 63) == 0) {
        int k = tid >> 4, l = tid & 15;
        float a = 0.f;
#pragma unroll 8
        for (int n = 0; n < 256; n++) a += Ss[n * 20 + k] * Ss[n * 20 + l];
        a *= (1.0f / 256.f);
        float off = (k != l) ? a : 0.f;
        float sq = off * off;
#pragma unroll
        for (int o = 16; o; o >>= 1) sq += __shfl_xor_sync(0xffffffffu, sq, o);
        if ((tid & 31) == 0) red[tid >> 5] = sq;

        if (tid < 16) {
            float u = 0.f;
#pragma unroll 8
            for (int n = 0; n < 256; n++) u += Ss[n * 20 + tid];
            us[tid] = u * (1.0f / 256.f);
        }
        __syncthreads();
        if (tid == 0) {
            float t = 0.f;
            for (int i = 0; i < 8; i++) t += red[i];
            d_orth[b] = 0.1f * t / 8192.0f;
            float usum = 0.f;
            for (int kk = 0; kk < 16; kk++) usum += us[kk];
            float lK = logf(1.0f / 16.0f);
            float kl = 0.f;
            for (int kk = 0; kk < 16; kk++) {
                float uc = fmaxf(us[kk] / (usum + 1e-8f), 1e-8f);
                kl += uc * (logf(uc) - lK);
            }
            d_usage[b] = 0.1f * kl / 32.0f;
            __threadfence();
            int prev = atomicAdd(&d_cnt, 1);
            if (prev == 31) {   // last one finalizes (deterministic order sum)
                __threadfence();
                float tt = d_greg;
                for (int bb = 0; bb < 32; bb++) tt += d_orth[bb];
                for (int bb = 0; bb < 32; bb++) tt += d_usage[bb];
                out[SCALAR_OFF] = tt;
                d_cnt = 0;      // reset for next replay
            }
        }
    }
}

// ---------------------------------------------------------------------------
extern "C" void kernel_launch(void* const* d_in, const int* in_sizes, int n_in,
                              void* d_out, int out_size) {
    const float* desc  = (const float*)d_in[0];
    const float* nv    = (const float*)d_in[1];
    const float* Wfus  = (const float*)d_in[2];
    const float* bfus  = (const float*)d_in[3];
    const float* Wslot = (const float*)d_in[4];
    const float* bslot = (const float*)d_in[5];
    const float* Gp    = (const float*)d_in[6];
    float* out = (float*)d_out;

    k_pre<<<33, 256>>>(Wslot, Wfus, Gp, bfus, bslot);
    k_S<<<256, 256>>>(desc, nv);
    k_Q<<<BB * HH * 8, 256>>>(out);
}